// round 1
// baseline (speedup 1.0000x reference)
#include <cuda_runtime.h>
#include <cstdint>

// Problem constants (fixed shapes per reference)
constexpr int B_ = 8;
constexpr int S_ = 4096;
constexpr int D_ = 2048;
constexpr int R_ = 4;
// Effective: per batch b, only adapters j = 4b..4b+3 contribute, weight 8/32 = 0.25.

constexpr int MT = 128;         // rows per stage-1 block
constexpr int KT = 32;          // K tile
constexpr int XS_STRIDE = 130;  // padded k-major x tile stride
constexpr int SROWS = 64;       // rows per stage-2 block

// Scratch: h[b*S + s][16]  (c = j*4 + r), 2 MB -> L2-resident
__device__ float g_h[(size_t)B_ * S_ * 16];

// ---- packed f32x2 helpers (sm_100+ PTX) ----
__device__ __forceinline__ unsigned long long fma2(unsigned long long a,
                                                   unsigned long long b,
                                                   unsigned long long c) {
    unsigned long long d;
    asm("fma.rn.f32x2 %0, %1, %2, %3;" : "=l"(d) : "l"(a), "l"(b), "l"(c));
    return d;
}
__device__ __forceinline__ unsigned long long pack2(float lo, float hi) {
    unsigned long long d;
    asm("mov.b64 %0, {%1, %2};" : "=l"(d) : "f"(lo), "f"(hi));
    return d;
}
__device__ __forceinline__ float2 unpack2(unsigned long long v) {
    float2 r;
    asm("mov.b64 {%0, %1}, %2;" : "=f"(r.x), "=f"(r.y) : "l"(v));
    return r;
}

// ============================================================================
// Stage 1: h[row][c] = sum_d x[row][d] * Bc[d][c]
//   Bc[d][j*4+r] = adapter_b[(4b+j)*D*R + d*R + r]
// Block: 256 threads, 128 rows x 16 cols, K loop in tiles of 32.
// Thread tile: 2 rows x 4 cols (2 f32x2 col-pairs).
// ============================================================================
__global__ __launch_bounds__(256) void lora_stage1(
    const float* __restrict__ x, const float* __restrict__ ab) {
    __shared__ float xs[KT * XS_STRIDE];  // xs[k*130 + m], k-major
    __shared__ float bs[KT][16];

    const int tid = threadIdx.x;
    const int row0 = blockIdx.x * MT;  // global row = b*S + s
    const int b = row0 / S_;

    // compute mapping: rg in [0,64) -> 2 rows, cg in [0,4) -> 4 cols
    const int rg = tid >> 2;
    const int cg = tid & 3;
    // loader mapping: lrow in [0,32), lk in [0,8) (4 floats each -> 32 k)
    const int lrow = tid >> 3;
    const int lk = tid & 7;

    const float* bbase = ab + (size_t)(4 * b) * D_ * R_;
    const float* xload = x + (size_t)(row0 + lrow) * D_ + lk * 4;

    unsigned long long acc00 = 0ull, acc01 = 0ull, acc10 = 0ull, acc11 = 0ull;

    for (int k0 = 0; k0 < D_; k0 += KT) {
        // B tile: 32 k x 16 c ; threads 0..127, one float4 each
        if (tid < 128) {
            const int kk = tid >> 2;
            const int j = tid & 3;
            float4 v = *(const float4*)(bbase + (size_t)j * (D_ * R_) +
                                        (size_t)(k0 + kk) * R_);
            *(float4*)&bs[kk][j * 4] = v;
        }
        // x tile: 128 rows x 32 k, transposed to k-major
#pragma unroll
        for (int rr = 0; rr < 4; rr++) {
            float4 v = *(const float4*)(xload + (size_t)rr * 32 * D_ + k0);
            const int m = lrow + rr * 32;
            const int kb = lk * 4;
            xs[(kb + 0) * XS_STRIDE + m] = v.x;
            xs[(kb + 1) * XS_STRIDE + m] = v.y;
            xs[(kb + 2) * XS_STRIDE + m] = v.z;
            xs[(kb + 3) * XS_STRIDE + m] = v.w;
        }
        __syncthreads();

#pragma unroll
        for (int kk = 0; kk < KT; kk++) {
            float2 xv = *(const float2*)&xs[kk * XS_STRIDE + rg * 2];
            unsigned long long b01 =
                *(const unsigned long long*)&bs[kk][cg * 4];
            unsigned long long b23 =
                *(const unsigned long long*)&bs[kk][cg * 4 + 2];
            unsigned long long x0 = pack2(xv.x, xv.x);
            unsigned long long x1 = pack2(xv.y, xv.y);
            acc00 = fma2(x0, b01, acc00);
            acc01 = fma2(x0, b23, acc01);
            acc10 = fma2(x1, b01, acc10);
            acc11 = fma2(x1, b23, acc11);
        }
        __syncthreads();
    }

    // write h: rows row0 + rg*2 + {0,1}, cols cg*4..cg*4+3
    {
        float2 lo = unpack2(acc00);
        float2 hi = unpack2(acc01);
        float4 v = make_float4(lo.x, lo.y, hi.x, hi.y);
        *(float4*)(g_h + (size_t)(row0 + rg * 2 + 0) * 16 + cg * 4) = v;
    }
    {
        float2 lo = unpack2(acc10);
        float2 hi = unpack2(acc11);
        float4 v = make_float4(lo.x, lo.y, hi.x, hi.y);
        *(float4*)(g_h + (size_t)(row0 + rg * 2 + 1) * 16 + cg * 4) = v;
    }
}

// ============================================================================
// Stage 2: out[row][d] = relu( 0.25 * sum_c h[row][c] * Ac[c][d] )
//   Ac[j*4+r][d] = adapter_a[(4b+j)*R*D + r*D + d]
// Block: 512 threads, each owns 4 consecutive d (A slice in registers),
// loops SROWS=64 rows with h broadcast from smem (pre-duplicated, pre-scaled).
// ============================================================================
__global__ __launch_bounds__(512) void lora_stage2(
    const float* __restrict__ aa, float* __restrict__ out) {
    __shared__ float2 hs[SROWS][16];  // (0.25*h, 0.25*h) pairs

    const int tid = threadIdx.x;
    const int b = blockIdx.y;
    const int s0 = blockIdx.x * SROWS;
    const size_t row0 = (size_t)b * S_ + s0;
    const int d0 = tid * 4;

    // Load A slice into registers: 16 c x 4 d -> 16 x 2 f32x2
    unsigned long long areg[16][2];
#pragma unroll
    for (int j = 0; j < 4; j++) {
#pragma unroll
        for (int r = 0; r < 4; r++) {
            float4 v = *(const float4*)(aa + (size_t)(4 * b + j) * (R_ * D_) +
                                        (size_t)r * D_ + d0);
            areg[j * 4 + r][0] = pack2(v.x, v.y);
            areg[j * 4 + r][1] = pack2(v.z, v.w);
        }
    }

    // Stage h tile into smem, duplicated and pre-scaled by 0.25
    for (int i = tid; i < SROWS * 16; i += 512) {
        float v = g_h[row0 * 16 + i] * 0.25f;
        ((float2*)hs)[i] = make_float2(v, v);
    }
    __syncthreads();

    for (int rr = 0; rr < SROWS; rr++) {
        unsigned long long acc0 = 0ull, acc1 = 0ull;
#pragma unroll
        for (int c = 0; c < 16; c++) {
            unsigned long long hv = *(const unsigned long long*)&hs[rr][c];
            acc0 = fma2(hv, areg[c][0], acc0);
            acc1 = fma2(hv, areg[c][1], acc1);
        }
        float2 v0 = unpack2(acc0);
        float2 v1 = unpack2(acc1);
        float4 o;
        o.x = fmaxf(v0.x, 0.0f);
        o.y = fmaxf(v0.y, 0.0f);
        o.z = fmaxf(v1.x, 0.0f);
        o.w = fmaxf(v1.y, 0.0f);
        *(float4*)(out + (row0 + rr) * D_ + d0) = o;
    }
}

extern "C" void kernel_launch(void* const* d_in, const int* in_sizes, int n_in,
                              void* d_out, int out_size) {
    const float* x = (const float*)d_in[0];
    const float* ab = (const float*)d_in[1];
    const float* aa = (const float*)d_in[2];
    float* out = (float*)d_out;

    lora_stage1<<<(B_ * S_) / MT, 256>>>(x, ab);

    dim3 g2(S_ / SROWS, B_);
    lora_stage2<<<g2, 512>>>(aa, out);
}